// round 16
// baseline (speedup 1.0000x reference)
#include <cuda_runtime.h>
#include <cuda_bf16.h>
#include <math.h>

// ---------------------------------------------------------------------------
// Problem constants
// ---------------------------------------------------------------------------
#define BATCH 256
#define TLEN  512
#define DIN   64
#define HID   128
#define G4    512              // 4*H
#define NCLS  12
#define MROWS (BATCH * TLEN)   // 131072

// ---- helpers ----
// pack two f32 -> bf16x2 (low = first arg)
__device__ __forceinline__ unsigned pack_bf16(float lo, float hi) {
    unsigned r;
    asm("cvt.rn.bf16x2.f32 %0, %1, %2;" : "=r"(r) : "f"(hi), "f"(lo));
    return r;
}
__device__ __forceinline__ void mma_bf16(float d[4], const unsigned a[4],
                                         unsigned b0, unsigned b1) {
    asm("mma.sync.aligned.m16n8k16.row.col.f32.bf16.bf16.f32 "
        "{%0,%1,%2,%3},{%4,%5,%6,%7},{%8,%9},{%0,%1,%2,%3};"
        : "+f"(d[0]), "+f"(d[1]), "+f"(d[2]), "+f"(d[3])
        : "r"(a[0]), "r"(a[1]), "r"(a[2]), "r"(a[3]), "r"(b0), "r"(b1));
}
__device__ __forceinline__ float tanh_fast(float x) {
    float y; asm("tanh.approx.f32 %0, %1;" : "=f"(y) : "f"(x)); return y;
}
__device__ __forceinline__ float sigm_fast(float x) {
    return fmaf(0.5f, tanh_fast(0.5f * x), 0.5f);
}
__device__ __forceinline__ unsigned smem_u32(const void* p) {
    unsigned a;
    asm("{ .reg .u64 t; cvta.to.shared.u64 t, %1; cvt.u32.u64 %0, t; }"
        : "=r"(a) : "l"(p));
    return a;
}
__device__ __forceinline__ void ldsm_x4(unsigned r[4], unsigned addr) {
    asm volatile("ldmatrix.sync.aligned.m8n8.x4.shared.b16 {%0,%1,%2,%3}, [%4];"
                 : "=r"(r[0]), "=r"(r[1]), "=r"(r[2]), "=r"(r[3]) : "r"(addr));
}
#define CP_ASYNC16(sm, gp) \
    asm volatile("cp.async.cg.shared.global [%0], [%1], 16;" :: "r"(sm), "l"(gp))
#define CP_COMMIT() asm volatile("cp.async.commit_group;")

// exact bf16x2 -> 2x fp32 (low, high)
__device__ __forceinline__ float bf_lo(unsigned u) { return __uint_as_float(u << 16); }
__device__ __forceinline__ float bf_hi(unsigned u) { return __uint_as_float(u & 0xffff0000u); }

// ---------------------------------------------------------------------------
// Scratch (device globals; allocation in kernel_launch is forbidden)
// ---------------------------------------------------------------------------
__device__ __align__(16) __nv_bfloat16 g_G0b[(size_t)2 * BATCH * TLEN * G4];  // layer0 gate pre-acts (bf16)
__device__ __align__(16) __nv_bfloat16 g_G1b[(size_t)2 * BATCH * TLEN * G4];  // layer1 gate pre-acts (bf16)
__device__ float g_HT[(size_t)2 * BATCH * HID];                               // layer1 final hidden
__device__ __align__(16) __nv_bfloat16 g_Xb [(size_t)BATCH * TLEN * DIN];     // X bf16
__device__ __align__(16) __nv_bfloat16 g_W0b[2 * G4 * DIN];                   // Wih0 bf16
__device__ __align__(16) __nv_bfloat16 g_W1b[2 * G4 * 2 * HID];               // Wih1 bf16
__device__ __align__(16) __nv_bfloat16 g_H1b[(size_t)BATCH * TLEN * 2 * HID]; // layer0 out bf16

// ---------------------------------------------------------------------------
// fp32 -> bf16 elementwise convert (pairs)
// ---------------------------------------------------------------------------
__global__ __launch_bounds__(256)
void f2bf_kernel(const float* __restrict__ src, __nv_bfloat16* __restrict__ dst,
                 int n2)
{
    int i = blockIdx.x * 256 + threadIdx.x;
    if (i < n2) {
        float2 v = ((const float2*)src)[i];
        ((unsigned*)dst)[i] = pack_bf16(v.x, v.y);
    }
}

// ---------------------------------------------------------------------------
// Gate-input GEMM, bf16 in/out, 3-stage cp.async ring + ldmatrix ("NT"):
//   G[dir][b][t][g] = bf16( A[m][:] . W[n][:] + bias[n] )
//   CTA tile 128x128, BK=32, 8 warps (4m x 2n) — R14 fragment layout,
//   but with a 3-deep cp.async pipeline (2 groups in flight while computing).
//   M-tiles entirely past len[b] are skipped (values never read downstream).
// ---------------------------------------------------------------------------
template <int KDIM>
__global__ __launch_bounds__(256, 2)
void gate_gemm_bf16(const __nv_bfloat16* __restrict__ A,
                    const __nv_bfloat16* __restrict__ W,
                    const float* __restrict__ bias,
                    const int*   __restrict__ lens,
                    __nv_bfloat16* __restrict__ G)
{
    constexpr int BM = 128, BN = 128, BK = 32, LD = 40;   // LD in b16 elems
    constexpr int NIT = KDIM / BK;
    constexpr int TILE = BM * LD;                          // b16 elems per tile
    extern __shared__ __align__(16) __nv_bfloat16 smem[];
    // ring of 3 stages, each stage = A tile + W tile
    __nv_bfloat16* As = smem;               // [3][TILE]
    __nv_bfloat16* Ws = smem + 3 * TILE;    // [3][TILE]

    const int m0 = blockIdx.y * BM;
    const int n0 = blockIdx.x * BN;
    const int b  = m0 >> 9;                 // 128 | 512 -> one batch per tile
    if ((m0 & 511) >= lens[b]) return;      // whole tile is padding

    const int tid  = threadIdx.x;
    const int lane = tid & 31;
    const int w    = tid >> 5;
    const int g    = lane >> 2;             // groupID
    const int t    = lane & 3;              // threadID in group
    const int wm   = w >> 1;                // m warp 0..3 (32 rows each)
    const int wn   = w & 1;                 // n warp 0..1 (64 cols each)

    // loader: thread covers 16 consecutive k (32 B) of one row via 2 cp.async
    const int lrow = tid >> 1;
    const int c16  = (tid & 1) * 16;
    const __nv_bfloat16* Agp = A + (size_t)(m0 + lrow) * KDIM + c16;
    const __nv_bfloat16* Wgp = W + (size_t)(n0 + lrow) * KDIM + c16;
    unsigned sA[3], sW[3];
#pragma unroll
    for (int st = 0; st < 3; st++) {
        sA[st] = smem_u32(As + st * TILE);
        sW[st] = smem_u32(Ws + st * TILE);
    }
    const unsigned soff = (lrow * LD + c16) * 2;   // byte offset in tile

    // ldmatrix lane -> matrix/row decomposition (tile-relative byte offsets)
    const int lq = lane >> 3;
    const int lr = lane & 7;
    const unsigned aoff0 = ((wm * 32 +      (lq & 1) * 8 + lr) * LD + (lq >> 1) * 8) * 2;
    const unsigned aoff1 = ((wm * 32 + 16 + (lq & 1) * 8 + lr) * LD + (lq >> 1) * 8) * 2;
    unsigned boff[4];
#pragma unroll
    for (int p = 0; p < 4; p++)
        boff[p] = ((wn * 64 + p * 16 + (lq & 1) * 8 + lr) * LD + (lq >> 1) * 8) * 2;

    float d[2][8][4];
#pragma unroll
    for (int mi = 0; mi < 2; mi++)
#pragma unroll
        for (int ni = 0; ni < 8; ni++)
#pragma unroll
            for (int c = 0; c < 4; c++) d[mi][ni][c] = 0.f;

    // prologue: issue stages 0 and 1
#pragma unroll
    for (int p = 0; p < 2 && p < NIT; p++) {
        CP_ASYNC16(sA[p] + soff,      Agp + p * BK);
        CP_ASYNC16(sA[p] + soff + 16, Agp + p * BK + 8);
        CP_ASYNC16(sW[p] + soff,      Wgp + p * BK);
        CP_ASYNC16(sW[p] + soff + 16, Wgp + p * BK + 8);
        CP_COMMIT();
    }

#pragma unroll
    for (int it = 0; it < NIT; it++) {
        if (it + 2 < NIT) {            // issue stage it+2 into ring slot
            const int st = (it + 2) % 3;
            const __nv_bfloat16* ag = Agp + (it + 2) * BK;
            const __nv_bfloat16* wg = Wgp + (it + 2) * BK;
            CP_ASYNC16(sA[st] + soff,      ag);
            CP_ASYNC16(sA[st] + soff + 16, ag + 8);
            CP_ASYNC16(sW[st] + soff,      wg);
            CP_ASYNC16(sW[st] + soff + 16, wg + 8);
            CP_COMMIT();
            asm volatile("cp.async.wait_group 2;");
        } else if (it + 1 < NIT) {
            asm volatile("cp.async.wait_group 1;");
        } else {
            asm volatile("cp.async.wait_group 0;");
        }
        __syncthreads();

        const unsigned bA = sA[it % 3];
        const unsigned bW = sW[it % 3];
#pragma unroll
        for (int kk = 0; kk < BK; kk += 16) {
            unsigned afr[2][4];
            ldsm_x4(afr[0], bA + aoff0 + kk * 2);
            ldsm_x4(afr[1], bA + aoff1 + kk * 2);
            unsigned bfr[8][2];
#pragma unroll
            for (int p = 0; p < 4; p++) {
                unsigned tmp[4];
                ldsm_x4(tmp, bW + boff[p] + kk * 2);
                bfr[2 * p][0]     = tmp[0];
                bfr[2 * p + 1][0] = tmp[1];
                bfr[2 * p][1]     = tmp[2];
                bfr[2 * p + 1][1] = tmp[3];
            }
#pragma unroll
            for (int ni = 0; ni < 8; ni++) {
                mma_bf16(d[0][ni], afr[0], bfr[ni][0], bfr[ni][1]);
                mma_bf16(d[1][ni], afr[1], bfr[ni][0], bfr[ni][1]);
            }
        }
        __syncthreads();
    }

    // epilogue: +bias, pack bf16x2, scatter to G[dir][b][t][g] (cols 2t,2t+1)
#pragma unroll
    for (int ni = 0; ni < 8; ni++) {
        const int col  = n0 + wn * 64 + ni * 8 + 2 * t;
        const int dirn = col >> 9;
        const int gg   = col & 511;
        const float2 bv = *(const float2*)(bias + col);
#pragma unroll
        for (int mi = 0; mi < 2; mi++) {
            const int m  = m0 + wm * 32 + mi * 16 + g;
            const int tt = m & 511;
            const size_t base = ((((size_t)dirn * BATCH + b) * TLEN) + tt) * G4 + gg;
            *(unsigned*)&G[base] =
                pack_bf16(d[mi][ni][0] + bv.x, d[mi][ni][1] + bv.y);   // row m
            *(unsigned*)&G[base + 8 * (size_t)G4] =
                pack_bf16(d[mi][ni][2] + bv.x, d[mi][ni][3] + bv.y);   // row m+8
        }
    }
}

// ---------------------------------------------------------------------------
// Tensor-core LSTM recurrence (R14 + split accumulator chains for ILP).
//   One CTA = (dir, 8 batches) -> 64 CTAs; 512 threads = 16 warps.
//   All 8 W k-steps in registers; gate inputs (bf16) prefetched one step
//   ahead and folded into acc init; ks 0-3 -> acc, ks 4-7 -> acc2 (chain
//   depth 4, ILP 8), merged on the 2 live columns; h1 written as bf16.
// ---------------------------------------------------------------------------
__global__ __launch_bounds__(512, 1)
void lstm_tc_kernel(const __nv_bfloat16* __restrict__ G,
                    const float* __restrict__ Whh,   // [2][512][128] fp32
                    const int*   __restrict__ lens,
                    __nv_bfloat16* __restrict__ h1,  // may be null (bf16 out)
                    float*       __restrict__ hT,    // may be null
                    int write_seq)
{
    __shared__ __align__(16) unsigned hfrag[2048];   // 2 buf x [ks][lane][4]

    const int tid  = threadIdx.x;
    const int lane = tid & 31;
    const int w    = tid >> 5;        // warp 0..15 -> units [8w, 8w+8)
    const int g    = lane >> 2;       // groupID == batch row (0..7)
    const int t    = lane & 3;        // threadID in group
    const int q0   = 8 * w + 2 * t;   // this lane's first unit

    const int dir = blockIdx.x >> 5;
    const int bb  = (blockIdx.x & 31) * 8;

    const float* Wd = Whh + (size_t)dir * G4 * HID;

    // ---- build W fragments, ALL in registers ----
    unsigned wreg[64];
#pragma unroll
    for (int ks = 0; ks < 8; ks++) {
#pragma unroll
        for (int gt = 0; gt < 4; gt++) {
            const float* row = Wd + (size_t)(gt * 128 + 8 * w + g) * HID + 16 * ks + 2 * t;
            float2 lo = *(const float2*)row;
            float2 hi = *(const float2*)(row + 8);
            wreg[(ks * 4 + gt) * 2]     = pack_bf16(lo.x, lo.y);
            wreg[(ks * 4 + gt) * 2 + 1] = pack_bf16(hi.x, hi.y);
        }
    }

    // zero both h-fragment buffers (rows 8-15 must stay zero forever)
    hfrag[tid]        = 0u;
    hfrag[tid + 512]  = 0u;
    hfrag[tid + 1024] = 0u;
    hfrag[tid + 1536] = 0u;

    const int len0 = lens[bb + g];        // this lane's batch
    int Tmax = 0;
#pragma unroll
    for (int i = 0; i < 8; i++) Tmax = max(Tmax, lens[bb + i]);

    const long long dstep = dir ? -(long long)G4 : (long long)G4;   // bf16 elems
    const __nv_bfloat16* p0 = G + (((size_t)(dir * BATCH + bb + g)) << 18)
                                + (size_t)(dir ? (len0 - 1) : 0) * G4;

    float c00 = 0.f, c01 = 0.f;
    float h00 = 0.f, h01 = 0.f;

    const int regA = (w & 1) ? 2 : 0;
    const int ksp  = w >> 1;

    __syncthreads();

    // prefetch gate inputs for step 0 (bf16x2 per gate type)
    unsigned gvu[4];
#pragma unroll
    for (int gt = 0; gt < 4; gt++)
        gvu[gt] = *(const unsigned*)(p0 + gt * 128 + q0);

    int cur = 0;
    for (int s = 0; s < Tmax; s++) {
        // advance pointer & prefetch step s+1 (hidden behind mma)
        if (s + 1 < len0) p0 += dstep;
        unsigned gnu[4];
#pragma unroll
        for (int gt = 0; gt < 4; gt++)
            gnu[gt] = *(const unsigned*)(p0 + gt * 128 + q0);

        // two accumulator sets -> mma chain depth 4 instead of 8
        float acc[4][4], acc2[4][4];
#pragma unroll
        for (int gt = 0; gt < 4; gt++) {
            acc[gt][0]  = bf_lo(gvu[gt]); acc[gt][1]  = bf_hi(gvu[gt]);
            acc[gt][2]  = 0.f;            acc[gt][3]  = 0.f;
            acc2[gt][0] = 0.f; acc2[gt][1] = 0.f;
            acc2[gt][2] = 0.f; acc2[gt][3] = 0.f;
        }

        const unsigned hbase = cur * 1024;
#pragma unroll
        for (int ks = 0; ks < 8; ks++) {
            uint4 av = *(const uint4*)&hfrag[hbase + ks * 128 + lane * 4];
            unsigned a[4] = { av.x, av.y, av.z, av.w };
            if (ks < 4) {
#pragma unroll
                for (int gt = 0; gt < 4; gt++)
                    mma_bf16(acc[gt],  a, wreg[(ks * 4 + gt) * 2],
                                          wreg[(ks * 4 + gt) * 2 + 1]);
            } else {
#pragma unroll
                for (int gt = 0; gt < 4; gt++)
                    mma_bf16(acc2[gt], a, wreg[(ks * 4 + gt) * 2],
                                          wreg[(ks * 4 + gt) * 2 + 1]);
            }
        }
#pragma unroll
        for (int gt = 0; gt < 4; gt++) {   // merge live columns only
            acc[gt][0] += acc2[gt][0];
            acc[gt][1] += acc2[gt][1];
        }

        // pointwise for batch bb+g (gate inputs already inside acc)
        if (s < len0) {
            c00 = fmaf(sigm_fast(acc[1][0]), c00,
                       sigm_fast(acc[0][0]) * tanh_fast(acc[2][0]));
            c01 = fmaf(sigm_fast(acc[1][1]), c01,
                       sigm_fast(acc[0][1]) * tanh_fast(acc[2][1]));
            h00 = sigm_fast(acc[3][0]) * tanh_fast(c00);
            h01 = sigm_fast(acc[3][1]) * tanh_fast(c01);
            if (write_seq) {
                const int tt = dir ? (len0 - 1 - s) : s;
                *(unsigned*)&h1[((size_t)(bb + g) * TLEN + tt) * (2 * HID)
                                + dir * HID + q0] = pack_bf16(h00, h01);
            }
        }

        // publish h (bf16x2) into the other buffer, A-frag row g
        hfrag[(cur ^ 1) * 1024 + ksp * 128 + lane * 4 + regA] = pack_bf16(h00, h01);
        __syncthreads();
        cur ^= 1;

#pragma unroll
        for (int gt = 0; gt < 4; gt++) gvu[gt] = gnu[gt];
    }

    if (hT)
        *(float2*)&hT[((size_t)(dir * BATCH + bb + g)) * HID + q0] = make_float2(h00, h01);

    if (write_seq) {
        // zero-fill padded region (reference masks hs to zero at t >= len)
        for (int qq = 0; qq < 8; qq++) {
            const int b  = bb + qq;
            const int lq = lens[b];
            const int ntail2 = (TLEN - lq) * 64;   // u32 units (2 bf16 each)
            for (int idx = tid; idx < ntail2; idx += 512) {
                const int tt = lq + (idx >> 6);
                const int kp = idx & 63;
                *(unsigned*)&h1[((size_t)b * TLEN + tt) * (2 * HID)
                                + dir * HID + kp * 2] = 0u;
            }
        }
    }
}

// ---------------------------------------------------------------------------
// FC + log_softmax.  h = concat([hT_backward, hT_forward]).
// ---------------------------------------------------------------------------
__global__ __launch_bounds__(32)
void fc_kernel(const float* __restrict__ HT,    // [2][256][128] (dir0=fwd, dir1=bwd)
               const float* __restrict__ Wfc,   // [12][256]
               const float* __restrict__ bfc,   // [12]
               float*       __restrict__ out)   // [256][12]
{
    const int b = blockIdx.x;
    const int c = threadIdx.x;
    float acc = 0.f;
    if (c < NCLS) {
        acc = bfc[c];
        const float* hb = HT + ((size_t)BATCH + b) * HID;  // backward (first half)
        const float* hf = HT + (size_t)b * HID;            // forward  (second half)
        const float* w  = Wfc + c * (2 * HID);
#pragma unroll 4
        for (int k = 0; k < HID; k++) acc = fmaf(w[k], hb[k], acc);
#pragma unroll 4
        for (int k = 0; k < HID; k++) acc = fmaf(w[HID + k], hf[k], acc);
    }
    float mx = (c < NCLS) ? acc : -3.4e38f;
#pragma unroll
    for (int o = 16; o; o >>= 1) mx = fmaxf(mx, __shfl_xor_sync(0xffffffffu, mx, o));
    float e = (c < NCLS) ? expf(acc - mx) : 0.f;
    float ssum = e;
#pragma unroll
    for (int o = 16; o; o >>= 1) ssum += __shfl_xor_sync(0xffffffffu, ssum, o);
    if (c < NCLS) out[b * NCLS + c] = acc - mx - logf(ssum);
}

// ---------------------------------------------------------------------------
// Launch
// ---------------------------------------------------------------------------
extern "C" void kernel_launch(void* const* d_in, const int* in_sizes, int n_in,
                              void* d_out, int out_size)
{
    const float* X    = (const float*)d_in[0];
    const int*   lens = (const int*)  d_in[1];
    const float* Wih0 = (const float*)d_in[2];
    const float* Whh0 = (const float*)d_in[3];
    const float* b0   = (const float*)d_in[4];
    const float* Wih1 = (const float*)d_in[5];
    const float* Whh1 = (const float*)d_in[6];
    const float* b1   = (const float*)d_in[7];
    const float* Wfc  = (const float*)d_in[8];
    const float* bfc  = (const float*)d_in[9];
    float* out = (float*)d_out;

    float *HT;
    __nv_bfloat16 *G0b, *G1b, *Xb, *W0b, *W1b, *H1b;
    cudaGetSymbolAddress((void**)&G0b, g_G0b);
    cudaGetSymbolAddress((void**)&G1b, g_G1b);
    cudaGetSymbolAddress((void**)&HT,  g_HT);
    cudaGetSymbolAddress((void**)&Xb,  g_Xb);
    cudaGetSymbolAddress((void**)&W0b, g_W0b);
    cudaGetSymbolAddress((void**)&W1b, g_W1b);
    cudaGetSymbolAddress((void**)&H1b, g_H1b);

    // dynamic smem: 3-stage ring, 2 tiles (A+W) of 128*40 bf16 per stage
    const int gsmem = 6 * 128 * 40 * 2;   // 61440 bytes
    cudaFuncSetAttribute(gate_gemm_bf16<DIN>,
                         cudaFuncAttributeMaxDynamicSharedMemorySize, gsmem);
    cudaFuncSetAttribute(gate_gemm_bf16<2 * HID>,
                         cudaFuncAttributeMaxDynamicSharedMemorySize, gsmem);

    dim3 gemm_grid(1024 / 128, MROWS / 128);   // 8 n-tiles x 1024 m-tiles

    // one-time fp32 -> bf16 conversions (X and input-projection weights)
    f2bf_kernel<<<(BATCH * TLEN * DIN / 2 + 255) / 256, 256>>>(X, Xb, BATCH * TLEN * DIN / 2);
    f2bf_kernel<<<(2 * G4 * DIN / 2 + 255) / 256, 256>>>(Wih0, W0b, 2 * G4 * DIN / 2);
    f2bf_kernel<<<(2 * G4 * 2 * HID / 2 + 255) / 256, 256>>>(Wih1, W1b, 2 * G4 * 2 * HID / 2);

    // layer 0: input gates (bf16 TC, 3-stage cp.async), recurrence -> H1 (bf16)
    gate_gemm_bf16<DIN><<<gemm_grid, 256, gsmem>>>(Xb, W0b, b0, lens, G0b);
    lstm_tc_kernel<<<64, 512>>>(G0b, Whh0, lens, H1b, nullptr, 1);

    // layer 1: input gates over H1 (bf16), recurrence -> final hiddens
    gate_gemm_bf16<2 * HID><<<gemm_grid, 256, gsmem>>>(H1b, W1b, b1, lens, G1b);
    lstm_tc_kernel<<<64, 512>>>(G1b, Whh1, lens, nullptr, HT, 0);

    // classifier head
    fc_kernel<<<BATCH, 32>>>(HT, Wfc, bfc, out);
}

// round 17
// speedup vs baseline: 1.2618x; 1.2618x over previous
#include <cuda_runtime.h>
#include <cuda_bf16.h>
#include <math.h>

// ---------------------------------------------------------------------------
// Problem constants
// ---------------------------------------------------------------------------
#define BATCH 256
#define TLEN  512
#define DIN   64
#define HID   128
#define G4    512              // 4*H
#define NCLS  12
#define MROWS (BATCH * TLEN)   // 131072

// ---- helpers ----
// pack two f32 -> bf16x2 (low = first arg)
__device__ __forceinline__ unsigned pack_bf16(float lo, float hi) {
    unsigned r;
    asm("cvt.rn.bf16x2.f32 %0, %1, %2;" : "=r"(r) : "f"(hi), "f"(lo));
    return r;
}
__device__ __forceinline__ void mma_bf16(float d[4], const unsigned a[4],
                                         unsigned b0, unsigned b1) {
    asm("mma.sync.aligned.m16n8k16.row.col.f32.bf16.bf16.f32 "
        "{%0,%1,%2,%3},{%4,%5,%6,%7},{%8,%9},{%0,%1,%2,%3};"
        : "+f"(d[0]), "+f"(d[1]), "+f"(d[2]), "+f"(d[3])
        : "r"(a[0]), "r"(a[1]), "r"(a[2]), "r"(a[3]), "r"(b0), "r"(b1));
}
__device__ __forceinline__ float tanh_fast(float x) {
    float y; asm("tanh.approx.f32 %0, %1;" : "=f"(y) : "f"(x)); return y;
}
__device__ __forceinline__ unsigned smem_u32(const void* p) {
    unsigned a;
    asm("{ .reg .u64 t; cvta.to.shared.u64 t, %1; cvt.u32.u64 %0, t; }"
        : "=r"(a) : "l"(p));
    return a;
}
__device__ __forceinline__ void ldsm_x4(unsigned r[4], unsigned addr) {
    asm volatile("ldmatrix.sync.aligned.m8n8.x4.shared.b16 {%0,%1,%2,%3}, [%4];"
                 : "=r"(r[0]), "=r"(r[1]), "=r"(r[2]), "=r"(r[3]) : "r"(addr));
}
#define CP_ASYNC16(sm, gp) \
    asm volatile("cp.async.cg.shared.global [%0], [%1], 16;" :: "r"(sm), "l"(gp))
#define CP_COMMIT() asm volatile("cp.async.commit_group;")

// exact bf16x2 -> 2x fp32 (low, high)
__device__ __forceinline__ float bf_lo(unsigned u) { return __uint_as_float(u << 16); }
__device__ __forceinline__ float bf_hi(unsigned u) { return __uint_as_float(u & 0xffff0000u); }

// packed sigmoid: {sigmoid(x0), sigmoid(x1)} as bf16x2 (one MUFU)
__device__ __forceinline__ unsigned sigm2_bf(float x0, float x1) {
    unsigned xh = pack_bf16(0.5f * x0, 0.5f * x1);
    unsigned th;
    asm("tanh.approx.bf16x2 %0, %1;" : "=r"(th) : "r"(xh));
    unsigned s;
    asm("fma.rn.bf16x2 %0, %1, %2, %3;"
        : "=r"(s) : "r"(th), "r"(0x3F003F00u), "r"(0x3F003F00u));
    return s;
}
// packed tanh: {tanh(x0), tanh(x1)} as bf16x2 (one MUFU)
__device__ __forceinline__ unsigned tanh2_bf(float x0, float x1) {
    unsigned xh = pack_bf16(x0, x1);
    unsigned th;
    asm("tanh.approx.bf16x2 %0, %1;" : "=r"(th) : "r"(xh));
    return th;
}

// ---------------------------------------------------------------------------
// Scratch (device globals; allocation in kernel_launch is forbidden)
// ---------------------------------------------------------------------------
__device__ __align__(16) __nv_bfloat16 g_G0b[(size_t)2 * BATCH * TLEN * G4];  // layer0 gate pre-acts (bf16)
__device__ __align__(16) __nv_bfloat16 g_G1b[(size_t)2 * BATCH * TLEN * G4];  // layer1 gate pre-acts (bf16)
__device__ float g_HT[(size_t)2 * BATCH * HID];                               // layer1 final hidden
__device__ __align__(16) __nv_bfloat16 g_Xb [(size_t)BATCH * TLEN * DIN];     // X bf16
__device__ __align__(16) __nv_bfloat16 g_W0b[2 * G4 * DIN];                   // Wih0 bf16
__device__ __align__(16) __nv_bfloat16 g_W1b[2 * G4 * 2 * HID];               // Wih1 bf16
__device__ __align__(16) __nv_bfloat16 g_H1b[(size_t)BATCH * TLEN * 2 * HID]; // layer0 out bf16

// ---------------------------------------------------------------------------
// fp32 -> bf16 elementwise convert (pairs)
// ---------------------------------------------------------------------------
__global__ __launch_bounds__(256)
void f2bf_kernel(const float* __restrict__ src, __nv_bfloat16* __restrict__ dst,
                 int n2)
{
    int i = blockIdx.x * 256 + threadIdx.x;
    if (i < n2) {
        float2 v = ((const float2*)src)[i];
        ((unsigned*)dst)[i] = pack_bf16(v.x, v.y);
    }
}

// ---------------------------------------------------------------------------
// Gate-input GEMM, bf16 in/out, 2-stage cp.async pipeline + ldmatrix ("NT")
//   — exact R14 configuration (proven 91 us for KDIM=64).
//   G[dir][b][t][g] = bf16( A[m][:] . W[n][:] + bias[n] )
//   CTA tile 128x128, BK=32, 8 warps (4m x 2n), warp tile 32x64.
//   Smem rows padded to 40 b16 (80 B) -> bank-distinct ldmatrix phases.
//   M-tiles entirely past len[b] are skipped (values never read downstream).
// ---------------------------------------------------------------------------
template <int KDIM>
__global__ __launch_bounds__(256, 2)
void gate_gemm_bf16(const __nv_bfloat16* __restrict__ A,
                    const __nv_bfloat16* __restrict__ W,
                    const float* __restrict__ bias,
                    const int*   __restrict__ lens,
                    __nv_bfloat16* __restrict__ G)
{
    constexpr int BM = 128, BN = 128, BK = 32, LD = 40;   // LD in b16 elems
    constexpr int NIT = KDIM / BK;
    __shared__ __align__(16) __nv_bfloat16 As[2][BM * LD];
    __shared__ __align__(16) __nv_bfloat16 Ws[2][BN * LD];

    const int m0 = blockIdx.y * BM;
    const int n0 = blockIdx.x * BN;
    const int b  = m0 >> 9;                 // 128 | 512 -> one batch per tile
    if ((m0 & 511) >= lens[b]) return;      // whole tile is padding

    const int tid  = threadIdx.x;
    const int lane = tid & 31;
    const int w    = tid >> 5;
    const int g    = lane >> 2;             // groupID
    const int t    = lane & 3;              // threadID in group
    const int wm   = w >> 1;                // m warp 0..3 (32 rows each)
    const int wn   = w & 1;                 // n warp 0..1 (64 cols each)

    // loader: thread covers 16 consecutive k (32 B) of one row via 2 cp.async
    const int lrow = tid >> 1;
    const int c16  = (tid & 1) * 16;
    const __nv_bfloat16* Agp = A + (size_t)(m0 + lrow) * KDIM + c16;
    const __nv_bfloat16* Wgp = W + (size_t)(n0 + lrow) * KDIM + c16;
    const unsigned sAb[2] = { smem_u32(&As[0][0]), smem_u32(&As[1][0]) };
    const unsigned sWb[2] = { smem_u32(&Ws[0][0]), smem_u32(&Ws[1][0]) };
    const unsigned soff   = (lrow * LD + c16) * 2;   // byte offset in tile

    // ldmatrix lane -> matrix/row decomposition (tile-relative byte offsets)
    const int lq = lane >> 3;
    const int lr = lane & 7;
    const unsigned aoff0 = ((wm * 32 +      (lq & 1) * 8 + lr) * LD + (lq >> 1) * 8) * 2;
    const unsigned aoff1 = ((wm * 32 + 16 + (lq & 1) * 8 + lr) * LD + (lq >> 1) * 8) * 2;
    unsigned boff[4];
#pragma unroll
    for (int p = 0; p < 4; p++)
        boff[p] = ((wn * 64 + p * 16 + (lq & 1) * 8 + lr) * LD + (lq >> 1) * 8) * 2;

    float d[2][8][4];
#pragma unroll
    for (int mi = 0; mi < 2; mi++)
#pragma unroll
        for (int ni = 0; ni < 8; ni++)
#pragma unroll
            for (int c = 0; c < 4; c++) d[mi][ni][c] = 0.f;

    // prologue: issue stage 0
    {
        CP_ASYNC16(sAb[0] + soff,      Agp);
        CP_ASYNC16(sAb[0] + soff + 16, Agp + 8);
        CP_ASYNC16(sWb[0] + soff,      Wgp);
        CP_ASYNC16(sWb[0] + soff + 16, Wgp + 8);
        CP_COMMIT();
    }

#pragma unroll
    for (int it = 0; it < NIT; it++) {
        if (it + 1 < NIT) {   // issue next stage into the other buffer
            const int nb = (it + 1) & 1;
            const __nv_bfloat16* ag = Agp + (it + 1) * BK;
            const __nv_bfloat16* wg = Wgp + (it + 1) * BK;
            CP_ASYNC16(sAb[nb] + soff,      ag);
            CP_ASYNC16(sAb[nb] + soff + 16, ag + 8);
            CP_ASYNC16(sWb[nb] + soff,      wg);
            CP_ASYNC16(sWb[nb] + soff + 16, wg + 8);
            CP_COMMIT();
            asm volatile("cp.async.wait_group 1;");
        } else {
            asm volatile("cp.async.wait_group 0;");
        }
        __syncthreads();

        const unsigned bA = sAb[it & 1];
        const unsigned bW = sWb[it & 1];
#pragma unroll
        for (int kk = 0; kk < BK; kk += 16) {
            unsigned afr[2][4];
            ldsm_x4(afr[0], bA + aoff0 + kk * 2);
            ldsm_x4(afr[1], bA + aoff1 + kk * 2);
            unsigned bfr[8][2];
#pragma unroll
            for (int p = 0; p < 4; p++) {
                unsigned tmp[4];
                ldsm_x4(tmp, bW + boff[p] + kk * 2);
                bfr[2 * p][0]     = tmp[0];
                bfr[2 * p + 1][0] = tmp[1];
                bfr[2 * p][1]     = tmp[2];
                bfr[2 * p + 1][1] = tmp[3];
            }
#pragma unroll
            for (int ni = 0; ni < 8; ni++) {
                mma_bf16(d[0][ni], afr[0], bfr[ni][0], bfr[ni][1]);
                mma_bf16(d[1][ni], afr[1], bfr[ni][0], bfr[ni][1]);
            }
        }
        __syncthreads();
    }

    // epilogue: +bias, pack bf16x2, scatter to G[dir][b][t][g] (cols 2t,2t+1)
#pragma unroll
    for (int ni = 0; ni < 8; ni++) {
        const int col  = n0 + wn * 64 + ni * 8 + 2 * t;
        const int dirn = col >> 9;
        const int gg   = col & 511;
        const float2 bv = *(const float2*)(bias + col);
#pragma unroll
        for (int mi = 0; mi < 2; mi++) {
            const int m  = m0 + wm * 32 + mi * 16 + g;
            const int tt = m & 511;
            const size_t base = ((((size_t)dirn * BATCH + b) * TLEN) + tt) * G4 + gg;
            *(unsigned*)&G[base] =
                pack_bf16(d[mi][ni][0] + bv.x, d[mi][ni][1] + bv.y);   // row m
            *(unsigned*)&G[base + 8 * (size_t)G4] =
                pack_bf16(d[mi][ni][2] + bv.x, d[mi][ni][3] + bv.y);   // row m+8
        }
    }
}

// ---------------------------------------------------------------------------
// Tensor-core LSTM recurrence (R14 structure + packed-MUFU pointwise).
//   One CTA = (dir, 8 batches) -> 64 CTAs; 512 threads = 16 warps.
//   All 8 W k-steps in registers; gate inputs (bf16) prefetched one step
//   ahead and folded into the mma acc init (cols 0,1); acc cols 2,3 are
//   dead (batches 8-15 don't exist) and are never re-zeroed.
//   Gate nonlinearities in tanh.approx.bf16x2 (6 MUFU/lane/step vs 10);
//   cell state c stays exact fp32.  h1 written as bf16.
// ---------------------------------------------------------------------------
__global__ __launch_bounds__(512, 1)
void lstm_tc_kernel(const __nv_bfloat16* __restrict__ G,
                    const float* __restrict__ Whh,   // [2][512][128] fp32
                    const int*   __restrict__ lens,
                    __nv_bfloat16* __restrict__ h1,  // may be null (bf16 out)
                    float*       __restrict__ hT,    // may be null
                    int write_seq)
{
    __shared__ __align__(16) unsigned hfrag[2048];   // 2 buf x [ks][lane][4]

    const int tid  = threadIdx.x;
    const int lane = tid & 31;
    const int w    = tid >> 5;        // warp 0..15 -> units [8w, 8w+8)
    const int g    = lane >> 2;       // groupID == batch row (0..7)
    const int t    = lane & 3;        // threadID in group
    const int q0   = 8 * w + 2 * t;   // this lane's first unit

    const int dir = blockIdx.x >> 5;
    const int bb  = (blockIdx.x & 31) * 8;

    const float* Wd = Whh + (size_t)dir * G4 * HID;

    // ---- build W fragments, ALL in registers ----
    unsigned wreg[64];
#pragma unroll
    for (int ks = 0; ks < 8; ks++) {
#pragma unroll
        for (int gt = 0; gt < 4; gt++) {
            const float* row = Wd + (size_t)(gt * 128 + 8 * w + g) * HID + 16 * ks + 2 * t;
            float2 lo = *(const float2*)row;
            float2 hi = *(const float2*)(row + 8);
            wreg[(ks * 4 + gt) * 2]     = pack_bf16(lo.x, lo.y);
            wreg[(ks * 4 + gt) * 2 + 1] = pack_bf16(hi.x, hi.y);
        }
    }

    // zero both h-fragment buffers (rows 8-15 must stay zero forever)
    hfrag[tid]        = 0u;
    hfrag[tid + 512]  = 0u;
    hfrag[tid + 1024] = 0u;
    hfrag[tid + 1536] = 0u;

    const int len0 = lens[bb + g];        // this lane's batch
    int Tmax = 0;
#pragma unroll
    for (int i = 0; i < 8; i++) Tmax = max(Tmax, lens[bb + i]);

    const long long dstep = dir ? -(long long)G4 : (long long)G4;   // bf16 elems
    const __nv_bfloat16* p0 = G + (((size_t)(dir * BATCH + bb + g)) << 18)
                                + (size_t)(dir ? (len0 - 1) : 0) * G4;

    float c00 = 0.f, c01 = 0.f;
    float h00 = 0.f, h01 = 0.f;

    const int regA = (w & 1) ? 2 : 0;
    const int ksp  = w >> 1;

    __syncthreads();

    // prefetch gate inputs for step 0 (bf16x2 per gate type)
    unsigned gvu[4];
#pragma unroll
    for (int gt = 0; gt < 4; gt++)
        gvu[gt] = *(const unsigned*)(p0 + gt * 128 + q0);

    // accumulators live across steps; cols 2,3 are dead and never reset
    float acc[4][4];
#pragma unroll
    for (int gt = 0; gt < 4; gt++)
#pragma unroll
        for (int c = 0; c < 4; c++) acc[gt][c] = 0.f;

    int cur = 0;
    for (int s = 0; s < Tmax; s++) {
        // advance pointer & prefetch step s+1 (hidden behind mma)
        if (s + 1 < len0) p0 += dstep;
        unsigned gnu[4];
#pragma unroll
        for (int gt = 0; gt < 4; gt++)
            gnu[gt] = *(const unsigned*)(p0 + gt * 128 + q0);

        // re-init only the live columns (gate inputs folded in)
#pragma unroll
        for (int gt = 0; gt < 4; gt++) {
            acc[gt][0] = bf_lo(gvu[gt]);
            acc[gt][1] = bf_hi(gvu[gt]);
        }

        const unsigned hbase = cur * 1024;
#pragma unroll
        for (int ks = 0; ks < 8; ks++) {
            uint4 av = *(const uint4*)&hfrag[hbase + ks * 128 + lane * 4];
            unsigned a[4] = { av.x, av.y, av.z, av.w };
#pragma unroll
            for (int gt = 0; gt < 4; gt++)
                mma_bf16(acc[gt], a, wreg[(ks * 4 + gt) * 2],
                                     wreg[(ks * 4 + gt) * 2 + 1]);
        }

        // pointwise for batch bb+g: packed bf16x2 nonlinearities, fp32 c
        if (s < len0) {
            const unsigned si = sigm2_bf(acc[0][0], acc[0][1]);
            const unsigned sf = sigm2_bf(acc[1][0], acc[1][1]);
            const unsigned tg = tanh2_bf(acc[2][0], acc[2][1]);
            const unsigned so = sigm2_bf(acc[3][0], acc[3][1]);
            c00 = fmaf(bf_lo(sf), c00, bf_lo(si) * bf_lo(tg));
            c01 = fmaf(bf_hi(sf), c01, bf_hi(si) * bf_hi(tg));
            h00 = bf_lo(so) * tanh_fast(c00);
            h01 = bf_hi(so) * tanh_fast(c01);
            if (write_seq) {
                const int tt = dir ? (len0 - 1 - s) : s;
                *(unsigned*)&h1[((size_t)(bb + g) * TLEN + tt) * (2 * HID)
                                + dir * HID + q0] = pack_bf16(h00, h01);
            }
        }

        // publish h (bf16x2) into the other buffer, A-frag row g
        hfrag[(cur ^ 1) * 1024 + ksp * 128 + lane * 4 + regA] = pack_bf16(h00, h01);
        __syncthreads();
        cur ^= 1;

#pragma unroll
        for (int gt = 0; gt < 4; gt++) gvu[gt] = gnu[gt];
    }

    if (hT)
        *(float2*)&hT[((size_t)(dir * BATCH + bb + g)) * HID + q0] = make_float2(h00, h01);

    if (write_seq) {
        // zero-fill padded region (reference masks hs to zero at t >= len)
        for (int qq = 0; qq < 8; qq++) {
            const int b  = bb + qq;
            const int lq = lens[b];
            const int ntail2 = (TLEN - lq) * 64;   // u32 units (2 bf16 each)
            for (int idx = tid; idx < ntail2; idx += 512) {
                const int tt = lq + (idx >> 6);
                const int kp = idx & 63;
                *(unsigned*)&h1[((size_t)b * TLEN + tt) * (2 * HID)
                                + dir * HID + kp * 2] = 0u;
            }
        }
    }
}

// ---------------------------------------------------------------------------
// FC + log_softmax.  h = concat([hT_backward, hT_forward]).
// ---------------------------------------------------------------------------
__global__ __launch_bounds__(32)
void fc_kernel(const float* __restrict__ HT,    // [2][256][128] (dir0=fwd, dir1=bwd)
               const float* __restrict__ Wfc,   // [12][256]
               const float* __restrict__ bfc,   // [12]
               float*       __restrict__ out)   // [256][12]
{
    const int b = blockIdx.x;
    const int c = threadIdx.x;
    float acc = 0.f;
    if (c < NCLS) {
        acc = bfc[c];
        const float* hb = HT + ((size_t)BATCH + b) * HID;  // backward (first half)
        const float* hf = HT + (size_t)b * HID;            // forward  (second half)
        const float* w  = Wfc + c * (2 * HID);
#pragma unroll 4
        for (int k = 0; k < HID; k++) acc = fmaf(w[k], hb[k], acc);
#pragma unroll 4
        for (int k = 0; k < HID; k++) acc = fmaf(w[HID + k], hf[k], acc);
    }
    float mx = (c < NCLS) ? acc : -3.4e38f;
#pragma unroll
    for (int o = 16; o; o >>= 1) mx = fmaxf(mx, __shfl_xor_sync(0xffffffffu, mx, o));
    float e = (c < NCLS) ? expf(acc - mx) : 0.f;
    float ssum = e;
#pragma unroll
    for (int o = 16; o; o >>= 1) ssum += __shfl_xor_sync(0xffffffffu, ssum, o);
    if (c < NCLS) out[b * NCLS + c] = acc - mx - logf(ssum);
}

// ---------------------------------------------------------------------------
// Launch
// ---------------------------------------------------------------------------
extern "C" void kernel_launch(void* const* d_in, const int* in_sizes, int n_in,
                              void* d_out, int out_size)
{
    const float* X    = (const float*)d_in[0];
    const int*   lens = (const int*)  d_in[1];
    const float* Wih0 = (const float*)d_in[2];
    const float* Whh0 = (const float*)d_in[3];
    const float* b0   = (const float*)d_in[4];
    const float* Wih1 = (const float*)d_in[5];
    const float* Whh1 = (const float*)d_in[6];
    const float* b1   = (const float*)d_in[7];
    const float* Wfc  = (const float*)d_in[8];
    const float* bfc  = (const float*)d_in[9];
    float* out = (float*)d_out;

    float *HT;
    __nv_bfloat16 *G0b, *G1b, *Xb, *W0b, *W1b, *H1b;
    cudaGetSymbolAddress((void**)&G0b, g_G0b);
    cudaGetSymbolAddress((void**)&G1b, g_G1b);
    cudaGetSymbolAddress((void**)&HT,  g_HT);
    cudaGetSymbolAddress((void**)&Xb,  g_Xb);
    cudaGetSymbolAddress((void**)&W0b, g_W0b);
    cudaGetSymbolAddress((void**)&W1b, g_W1b);
    cudaGetSymbolAddress((void**)&H1b, g_H1b);

    dim3 gemm_grid(1024 / 128, MROWS / 128);   // 8 n-tiles x 1024 m-tiles

    // one-time fp32 -> bf16 conversions (X and input-projection weights)
    f2bf_kernel<<<(BATCH * TLEN * DIN / 2 + 255) / 256, 256>>>(X, Xb, BATCH * TLEN * DIN / 2);
    f2bf_kernel<<<(2 * G4 * DIN / 2 + 255) / 256, 256>>>(Wih0, W0b, 2 * G4 * DIN / 2);
    f2bf_kernel<<<(2 * G4 * 2 * HID / 2 + 255) / 256, 256>>>(Wih1, W1b, 2 * G4 * 2 * HID / 2);

    // layer 0: input gates (bf16 TC, cp.async), recurrence -> H1 (bf16)
    gate_gemm_bf16<DIN><<<gemm_grid, 256>>>(Xb, W0b, b0, lens, G0b);
    lstm_tc_kernel<<<64, 512>>>(G0b, Whh0, lens, H1b, nullptr, 1);

    // layer 1: input gates over H1 (bf16), recurrence -> final hiddens
    gate_gemm_bf16<2 * HID><<<gemm_grid, 256>>>(H1b, W1b, b1, lens, G1b);
    lstm_tc_kernel<<<64, 512>>>(G1b, Whh1, lens, nullptr, HT, 0);

    // classifier head
    fc_kernel<<<BATCH, 32>>>(HT, Wfc, bfc, out);
}